// round 1
// baseline (speedup 1.0000x reference)
#include <cuda_runtime.h>
#include <math.h>

#define NB   8
#define NF   2048
#define NK   4096
#define SEQ  6144
#define CIN  256
#define CKQ  64
#define COUT 256

// Scratch (device globals — no allocation allowed in kernel_launch)
__device__ float g_q[(size_t)NB * NF * CKQ];    //  4 MB
__device__ float g_k[(size_t)NB * NK * CKQ];    //  8 MB
__device__ float g_v[(size_t)NB * NK * COUT];   // 32 MB

// ---------------------------------------------------------------------------
// Projection GEMM: C[M,N] = rows(A)[M,256] @ W[N,256]^T + bias
// MODE 0: rows are the "fill" rows of each batch; MODE 1: the "keep" rows.
// Tile 64x64, k-step 16, 256 threads, 4x4 per-thread microtile.
// ---------------------------------------------------------------------------
template <int MODE>
__global__ void __launch_bounds__(256) proj_kernel(
    const float* __restrict__ A, const float* __restrict__ W,
    const float* __restrict__ bias, float* __restrict__ C, int N)
{
    __shared__ float As[16][68];
    __shared__ float Ws[16][68];

    const int m0 = blockIdx.y * 64;
    const int n0 = blockIdx.x * 64;
    const int t  = threadIdx.x;
    const int tx = t & 15, ty = t >> 4;

    float acc[4][4] = {};

    // load mapping: thread t loads row r, 4 contiguous k values
    const int r  = t >> 2;
    const int kq = (t & 3) * 4;
    int grow;
    {
        int m = m0 + r;
        if (MODE == 0) grow = (m >> 11) * SEQ + (m & (NF - 1));
        else           grow = (m >> 12) * SEQ + NF + (m & (NK - 1));
    }
    const float* Arow = A + (size_t)grow * CIN;
    const float* Wrow = W + (size_t)(n0 + r) * CIN;

    for (int k0 = 0; k0 < CIN; k0 += 16) {
        float4 av = *(const float4*)(Arow + k0 + kq);
        float4 wv = *(const float4*)(Wrow + k0 + kq);
        As[kq + 0][r] = av.x; As[kq + 1][r] = av.y;
        As[kq + 2][r] = av.z; As[kq + 3][r] = av.w;
        Ws[kq + 0][r] = wv.x; Ws[kq + 1][r] = wv.y;
        Ws[kq + 2][r] = wv.z; Ws[kq + 3][r] = wv.w;
        __syncthreads();
        #pragma unroll
        for (int kk = 0; kk < 16; kk++) {
            float4 a = *(const float4*)&As[kk][ty * 4];
            float4 b = *(const float4*)&Ws[kk][tx * 4];
            acc[0][0] += a.x * b.x; acc[0][1] += a.x * b.y; acc[0][2] += a.x * b.z; acc[0][3] += a.x * b.w;
            acc[1][0] += a.y * b.x; acc[1][1] += a.y * b.y; acc[1][2] += a.y * b.z; acc[1][3] += a.y * b.w;
            acc[2][0] += a.z * b.x; acc[2][1] += a.z * b.y; acc[2][2] += a.z * b.z; acc[2][3] += a.z * b.w;
            acc[3][0] += a.w * b.x; acc[3][1] += a.w * b.y; acc[3][2] += a.w * b.z; acc[3][3] += a.w * b.w;
        }
        __syncthreads();
    }

    float4 bz = *(const float4*)(bias + n0 + tx * 4);
    #pragma unroll
    for (int i = 0; i < 4; i++) {
        int m = m0 + ty * 4 + i;
        float4 o;
        o.x = acc[i][0] + bz.x;
        o.y = acc[i][1] + bz.y;
        o.z = acc[i][2] + bz.z;
        o.w = acc[i][3] + bz.w;
        *(float4*)(C + (size_t)m * N + n0 + tx * 4) = o;
    }
}

// ---------------------------------------------------------------------------
// Flash-style attention: one block = (batch b, 64 query rows).
// Online softmax over 64 key chunks of 64 keys each.
// 256 threads; O tile 64x256 in registers (4 rows x 16 cols per thread).
// ---------------------------------------------------------------------------
__global__ void __launch_bounds__(256) attn_kernel(
    const float* __restrict__ gq, const float* __restrict__ gk,
    const float* __restrict__ gv, float* __restrict__ out)
{
    extern __shared__ float sm[];
    float* qsT  = sm;                 // [64 d][68]   q transposed
    float* ksT  = qsT + 64 * 68;      // [64 d][68]   k transposed
    float* sP   = ksT + 64 * 68;      // [64 q][68]   scores -> probs
    float* vs   = sP + 64 * 68;       // [64 k][256]  v chunk
    float* mrow = vs + 64 * 256;      // [64]
    float* lrow = mrow + 64;          // [64]
    float* arow = lrow + 64;          // [64]

    const int t  = threadIdx.x;
    const int b  = blockIdx.y;
    const int q0 = blockIdx.x * 64;
    const int tx = t & 15, ty = t >> 4;

    // Load Q tile transposed (d-major)
    #pragma unroll
    for (int rep = 0; rep < 4; rep++) {
        int lin = rep * 1024 + t * 4;
        int r = lin >> 6, d = lin & 63;
        float4 v = *(const float4*)(gq + (size_t)(b * NF + q0 + r) * CKQ + d);
        qsT[(d + 0) * 68 + r] = v.x;
        qsT[(d + 1) * 68 + r] = v.y;
        qsT[(d + 2) * 68 + r] = v.z;
        qsT[(d + 3) * 68 + r] = v.w;
    }
    if (t < 64) { mrow[t] = -INFINITY; lrow[t] = 0.f; }

    float O[4][16];
    #pragma unroll
    for (int i = 0; i < 4; i++)
        #pragma unroll
        for (int c = 0; c < 16; c++) O[i][c] = 0.f;

    __syncthreads();

    for (int ch = 0; ch < NK / 64; ch++) {
        const float* kbase = gk + (size_t)(b * NK + ch * 64) * CKQ;
        const float* vbase = gv + (size_t)(b * NK + ch * 64) * COUT;

        // Load K chunk transposed
        #pragma unroll
        for (int rep = 0; rep < 4; rep++) {
            int lin = rep * 1024 + t * 4;
            int r = lin >> 6, d = lin & 63;
            float4 v = *(const float4*)(kbase + r * CKQ + d);
            ksT[(d + 0) * 68 + r] = v.x;
            ksT[(d + 1) * 68 + r] = v.y;
            ksT[(d + 2) * 68 + r] = v.z;
            ksT[(d + 3) * 68 + r] = v.w;
        }
        // Load V chunk (row-major)
        #pragma unroll
        for (int rep = 0; rep < 16; rep++) {
            int lin = rep * 1024 + t * 4;
            int r = lin >> 8, c = lin & 255;
            *(float4*)(vs + r * 256 + c) = *(const float4*)(vbase + r * COUT + c);
        }
        __syncthreads();

        // S = Q @ K^T  (4x4 per thread)
        float acc[4][4] = {};
        #pragma unroll 8
        for (int d = 0; d < 64; d++) {
            float4 a  = *(const float4*)(qsT + d * 68 + ty * 4);
            float4 k4 = *(const float4*)(ksT + d * 68 + tx * 4);
            acc[0][0] += a.x * k4.x; acc[0][1] += a.x * k4.y; acc[0][2] += a.x * k4.z; acc[0][3] += a.x * k4.w;
            acc[1][0] += a.y * k4.x; acc[1][1] += a.y * k4.y; acc[1][2] += a.y * k4.z; acc[1][3] += a.y * k4.w;
            acc[2][0] += a.z * k4.x; acc[2][1] += a.z * k4.y; acc[2][2] += a.z * k4.z; acc[2][3] += a.z * k4.w;
            acc[3][0] += a.w * k4.x; acc[3][1] += a.w * k4.y; acc[3][2] += a.w * k4.z; acc[3][3] += a.w * k4.w;
        }
        #pragma unroll
        for (int i = 0; i < 4; i++) {
            float4 o;
            o.x = acc[i][0] * 0.125f; o.y = acc[i][1] * 0.125f;
            o.z = acc[i][2] * 0.125f; o.w = acc[i][3] * 0.125f;
            *(float4*)(sP + (ty * 4 + i) * 68 + tx * 4) = o;
        }
        __syncthreads();

        // Online softmax stats: 4 threads per row, 16 cols each
        {
            int r = t >> 2, c0 = (t & 3) * 16;
            float* srow = sP + r * 68 + c0;
            float mloc = srow[0];
            #pragma unroll
            for (int c = 1; c < 16; c++) mloc = fmaxf(mloc, srow[c]);
            mloc = fmaxf(mloc, __shfl_xor_sync(0xffffffffu, mloc, 1));
            mloc = fmaxf(mloc, __shfl_xor_sync(0xffffffffu, mloc, 2));
            float mold = mrow[r];
            float mnew = fmaxf(mold, mloc);
            float sum = 0.f;
            #pragma unroll
            for (int c = 0; c < 16; c++) {
                float p = __expf(srow[c] - mnew);
                srow[c] = p;
                sum += p;
            }
            sum += __shfl_xor_sync(0xffffffffu, sum, 1);
            sum += __shfl_xor_sync(0xffffffffu, sum, 2);
            if ((t & 3) == 0) {
                float al = __expf(mold - mnew);
                arow[r] = al;
                mrow[r] = mnew;
                lrow[r] = lrow[r] * al + sum;
            }
        }
        __syncthreads();

        // O = O*alpha + P @ V
        {
            float al[4];
            #pragma unroll
            for (int i = 0; i < 4; i++) al[i] = arow[ty * 4 + i];
            #pragma unroll
            for (int i = 0; i < 4; i++)
                #pragma unroll
                for (int c = 0; c < 16; c++) O[i][c] *= al[i];

            #pragma unroll 4
            for (int j = 0; j < 64; j++) {
                float p0 = sP[(ty * 4 + 0) * 68 + j];
                float p1 = sP[(ty * 4 + 1) * 68 + j];
                float p2 = sP[(ty * 4 + 2) * 68 + j];
                float p3 = sP[(ty * 4 + 3) * 68 + j];
                const float* vrow = vs + j * 256 + tx * 16;
                #pragma unroll
                for (int c4 = 0; c4 < 4; c4++) {
                    float4 v4 = *(const float4*)(vrow + c4 * 4);
                    O[0][c4 * 4 + 0] += p0 * v4.x; O[0][c4 * 4 + 1] += p0 * v4.y;
                    O[0][c4 * 4 + 2] += p0 * v4.z; O[0][c4 * 4 + 3] += p0 * v4.w;
                    O[1][c4 * 4 + 0] += p1 * v4.x; O[1][c4 * 4 + 1] += p1 * v4.y;
                    O[1][c4 * 4 + 2] += p1 * v4.z; O[1][c4 * 4 + 3] += p1 * v4.w;
                    O[2][c4 * 4 + 0] += p2 * v4.x; O[2][c4 * 4 + 1] += p2 * v4.y;
                    O[2][c4 * 4 + 2] += p2 * v4.z; O[2][c4 * 4 + 3] += p2 * v4.w;
                    O[3][c4 * 4 + 0] += p3 * v4.x; O[3][c4 * 4 + 1] += p3 * v4.y;
                    O[3][c4 * 4 + 2] += p3 * v4.z; O[3][c4 * 4 + 3] += p3 * v4.w;
                }
            }
        }
        __syncthreads();
    }

    // Normalize + write out (fill rows occupy the first NF rows of each batch)
    float linv[4];
    #pragma unroll
    for (int i = 0; i < 4; i++) linv[i] = 1.0f / lrow[ty * 4 + i];
    #pragma unroll
    for (int i = 0; i < 4; i++) {
        float* orow = out + (size_t)(b * SEQ + q0 + ty * 4 + i) * COUT + tx * 16;
        #pragma unroll
        for (int c4 = 0; c4 < 4; c4++) {
            float4 o;
            o.x = O[i][c4 * 4 + 0] * linv[i];
            o.y = O[i][c4 * 4 + 1] * linv[i];
            o.z = O[i][c4 * 4 + 2] * linv[i];
            o.w = O[i][c4 * 4 + 3] * linv[i];
            *(float4*)(orow + c4 * 4) = o;
        }
    }
}

// ---------------------------------------------------------------------------
// Copy keep rows (identity) into the output.
// ---------------------------------------------------------------------------
__global__ void __launch_bounds__(256) copy_keep_kernel(
    const float* __restrict__ f, float* __restrict__ out)
{
    int idx = blockIdx.x * blockDim.x + threadIdx.x;       // float4 index
    int kr = idx >> 6;                                      // keep row 0..32767
    int c  = (idx & 63) * 4;
    int b  = kr >> 12;
    int j  = kr & (NK - 1);
    size_t grow = (size_t)b * SEQ + NF + j;
    *(float4*)(out + grow * COUT + c) = *(const float4*)(f + grow * CIN + c);
}

// ---------------------------------------------------------------------------
extern "C" void kernel_launch(void* const* d_in, const int* in_sizes, int n_in,
                              void* d_out, int out_size)
{
    const float* features = (const float*)d_in[0];
    // d_in[1] = keep_flag (unused; layout is fixed)
    const float* Wq = (const float*)d_in[2];
    const float* bq = (const float*)d_in[3];
    const float* Wk = (const float*)d_in[4];
    const float* bk = (const float*)d_in[5];
    const float* Wv = (const float*)d_in[6];
    const float* bv = (const float*)d_in[7];
    float* out = (float*)d_out;

    void *pq, *pk, *pv;
    cudaGetSymbolAddress(&pq, g_q);
    cudaGetSymbolAddress(&pk, g_k);
    cudaGetSymbolAddress(&pv, g_v);

    // Projections
    proj_kernel<0><<<dim3(1, (NB * NF) / 64), 256>>>(features, Wq, bq, (float*)pq, CKQ);
    proj_kernel<1><<<dim3(1, (NB * NK) / 64), 256>>>(features, Wk, bk, (float*)pk, CKQ);
    proj_kernel<1><<<dim3(COUT / 64, (NB * NK) / 64), 256>>>(features, Wv, bv, (float*)pv, COUT);

    // Identity copy of keep rows
    copy_keep_kernel<<<(NB * NK * COUT / 4) / 256, 256>>>(features, out);

    // Attention
    const int smem_bytes = (3 * 64 * 68 + 64 * 256 + 3 * 64) * sizeof(float);
    cudaFuncSetAttribute(attn_kernel, cudaFuncAttributeMaxDynamicSharedMemorySize, smem_bytes);
    attn_kernel<<<dim3(NF / 64, NB), 256, smem_bytes>>>(
        (const float*)pq, (const float*)pk, (const float*)pv, out);
}

// round 4
// speedup vs baseline: 4.7925x; 4.7925x over previous
#include <cuda_runtime.h>
#include <math.h>
#include <stdint.h>

#define NB   8
#define NF   2048
#define NK   4096
#define SEQ  6144
#define CIN  256
#define CKQ  64
#define COUT 256

// Scratch (device globals — no allocation allowed in kernel_launch)
__device__ float g_q[(size_t)NB * NF * CKQ];    //  4 MB
__device__ float g_k[(size_t)NB * NK * CKQ];    //  8 MB
__device__ float g_v[(size_t)NB * NK * COUT];   // 32 MB

__device__ __forceinline__ unsigned f2tf(float x) {
    unsigned u;
    asm("cvt.rna.tf32.f32 %0, %1;" : "=r"(u) : "f"(x));
    return u;
}

__device__ __forceinline__ void mma8(float* c,
                                     unsigned a0, unsigned a1, unsigned a2, unsigned a3,
                                     unsigned b0, unsigned b1) {
    asm("mma.sync.aligned.m16n8k8.row.col.f32.tf32.tf32.f32 "
        "{%0,%1,%2,%3},{%4,%5,%6,%7},{%8,%9},{%0,%1,%2,%3};"
        : "+f"(c[0]), "+f"(c[1]), "+f"(c[2]), "+f"(c[3])
        : "r"(a0), "r"(a1), "r"(a2), "r"(a3), "r"(b0), "r"(b1));
}

// ---------------------------------------------------------------------------
// Projection GEMM via tf32 mma: C[M,N] = rows(A)[M,256] @ W[N,256]^T + bias
// Block tile 128x64, BK=32, 8 warps in 4x2 grid (warp tile 32x32).
// ---------------------------------------------------------------------------
template <int MODE>
__global__ void __launch_bounds__(256) proj_tc(
    const float* __restrict__ A, const float* __restrict__ W,
    const float* __restrict__ bias, float* __restrict__ C, int N)
{
    __shared__ unsigned As[128][36];
    __shared__ unsigned Ws[64][36];

    const int t = threadIdx.x, lane = t & 31, w = t >> 5;
    const int m0 = blockIdx.y * 128, n0 = blockIdx.x * 64;
    const int mw = (w & 3) * 32, nw = (w >> 2) * 32;
    const int lg = lane >> 2, lt = lane & 3;

    float acc[2][4][4] = {};

    // global load mapping
    const int ra = t >> 1, sa = (t & 1) * 16;
    int m = m0 + ra;
    int grow = (MODE == 0) ? (m >> 11) * SEQ + (m & (NF - 1))
                           : (m >> 12) * SEQ + NF + (m & (NK - 1));
    const float* Ag = A + (size_t)grow * CIN + sa;
    const int rw = t >> 2, sw = (t & 3) * 8;
    const float* Wg = W + (size_t)(n0 + rw) * CIN + sw;

    for (int k0 = 0; k0 < CIN; k0 += 32) {
        #pragma unroll
        for (int q = 0; q < 4; q++) {
            float4 v = *(const float4*)(Ag + k0 + q * 4);
            As[ra][sa + q * 4 + 0] = f2tf(v.x);
            As[ra][sa + q * 4 + 1] = f2tf(v.y);
            As[ra][sa + q * 4 + 2] = f2tf(v.z);
            As[ra][sa + q * 4 + 3] = f2tf(v.w);
        }
        #pragma unroll
        for (int q = 0; q < 2; q++) {
            float4 v = *(const float4*)(Wg + k0 + q * 4);
            Ws[rw][sw + q * 4 + 0] = f2tf(v.x);
            Ws[rw][sw + q * 4 + 1] = f2tf(v.y);
            Ws[rw][sw + q * 4 + 2] = f2tf(v.z);
            Ws[rw][sw + q * 4 + 3] = f2tf(v.w);
        }
        __syncthreads();

        #pragma unroll
        for (int ks = 0; ks < 4; ks++) {
            const int kk = ks * 8;
            unsigned a[2][4];
            #pragma unroll
            for (int mi = 0; mi < 2; mi++) {
                int r = mw + mi * 16 + lg;
                a[mi][0] = As[r][kk + lt];
                a[mi][1] = As[r + 8][kk + lt];
                a[mi][2] = As[r][kk + lt + 4];
                a[mi][3] = As[r + 8][kk + lt + 4];
            }
            #pragma unroll
            for (int ni = 0; ni < 4; ni++) {
                int rn = nw + ni * 8 + lg;
                unsigned b0 = Ws[rn][kk + lt];
                unsigned b1 = Ws[rn][kk + lt + 4];
                mma8(acc[0][ni], a[0][0], a[0][1], a[0][2], a[0][3], b0, b1);
                mma8(acc[1][ni], a[1][0], a[1][1], a[1][2], a[1][3], b0, b1);
            }
        }
        __syncthreads();
    }

    #pragma unroll
    for (int mi = 0; mi < 2; mi++) {
        #pragma unroll
        for (int ni = 0; ni < 4; ni++) {
            int col = n0 + nw + ni * 8 + 2 * lt;
            float2 bz = *(const float2*)(bias + col);
            int r0 = m0 + mw + mi * 16 + lg;
            float2 o0, o1;
            o0.x = acc[mi][ni][0] + bz.x; o0.y = acc[mi][ni][1] + bz.y;
            o1.x = acc[mi][ni][2] + bz.x; o1.y = acc[mi][ni][3] + bz.y;
            *(float2*)(C + (size_t)r0 * N + col) = o0;
            *(float2*)(C + (size_t)(r0 + 8) * N + col) = o1;
        }
    }
}

// ---------------------------------------------------------------------------
// Flash attention via tf32 mma. Block = (batch, 64 queries), 8 warps.
// QK warp grid 2x4 (32x16 per warp); PV warp grid 2x4 (32x64 per warp).
// ---------------------------------------------------------------------------
__global__ void __launch_bounds__(256) attn_tc(
    const float* __restrict__ gq, const float* __restrict__ gk,
    const float* __restrict__ gv, float* __restrict__ out)
{
    extern __shared__ char smraw[];
    unsigned* Qs = (unsigned*)smraw;        // [64][68] tf32
    unsigned* Ks = Qs + 64 * 68;            // [64][68] tf32
    unsigned* Vs = Ks + 64 * 68;            // [64][264] tf32
    float*    S  = (float*)(Vs + 64 * 264); // [64][68] fp32 scores -> tf32 P
    float* mrow = S + 64 * 68;
    float* lrow = mrow + 64;
    float* arow = lrow + 64;

    const int t = threadIdx.x, lane = t & 31, w = t >> 5;
    const int b = blockIdx.y, q0 = blockIdx.x * 64;
    const int lg = lane >> 2, lt = lane & 3;
    const int mw = (w & 1) * 32;        // row half (shared by QK and PV tiling)
    const int nws = (w >> 1) * 16;      // QK col group
    const int nwp = (w >> 1) * 64;      // PV col group

    // Load Q tile as tf32
    #pragma unroll
    for (int rep = 0; rep < 4; rep++) {
        int lin = rep * 1024 + t * 4;
        int r = lin >> 6, d = lin & 63;
        float4 v = *(const float4*)(gq + (size_t)(b * NF + q0 + r) * CKQ + d);
        Qs[r * 68 + d + 0] = f2tf(v.x);
        Qs[r * 68 + d + 1] = f2tf(v.y);
        Qs[r * 68 + d + 2] = f2tf(v.z);
        Qs[r * 68 + d + 3] = f2tf(v.w);
    }
    if (t < 64) { mrow[t] = -INFINITY; lrow[t] = 0.f; }

    float O[2][8][4] = {};
    __syncthreads();

    for (int ch = 0; ch < NK / 64; ch++) {
        const float* kb = gk + (size_t)(b * NK + ch * 64) * CKQ;
        const float* vb = gv + (size_t)(b * NK + ch * 64) * COUT;

        #pragma unroll
        for (int rep = 0; rep < 4; rep++) {
            int lin = rep * 1024 + t * 4;
            int r = lin >> 6, d = lin & 63;
            float4 v = *(const float4*)(kb + r * CKQ + d);
            Ks[r * 68 + d + 0] = f2tf(v.x);
            Ks[r * 68 + d + 1] = f2tf(v.y);
            Ks[r * 68 + d + 2] = f2tf(v.z);
            Ks[r * 68 + d + 3] = f2tf(v.w);
        }
        #pragma unroll
        for (int rep = 0; rep < 16; rep++) {
            int lin = rep * 1024 + t * 4;
            int r = lin >> 8, c = lin & 255;
            float4 v = *(const float4*)(vb + r * COUT + c);
            Vs[r * 264 + c + 0] = f2tf(v.x);
            Vs[r * 264 + c + 1] = f2tf(v.y);
            Vs[r * 264 + c + 2] = f2tf(v.z);
            Vs[r * 264 + c + 3] = f2tf(v.w);
        }
        __syncthreads();

        // ---- S = Q @ K^T ----
        float sc[2][2][4] = {};
        #pragma unroll
        for (int ks = 0; ks < 8; ks++) {
            const int kk = ks * 8;
            unsigned a[2][4];
            #pragma unroll
            for (int mi = 0; mi < 2; mi++) {
                int r = mw + mi * 16 + lg;
                a[mi][0] = Qs[r * 68 + kk + lt];
                a[mi][1] = Qs[(r + 8) * 68 + kk + lt];
                a[mi][2] = Qs[r * 68 + kk + lt + 4];
                a[mi][3] = Qs[(r + 8) * 68 + kk + lt + 4];
            }
            #pragma unroll
            for (int ni = 0; ni < 2; ni++) {
                int rn = nws + ni * 8 + lg;
                unsigned b0 = Ks[rn * 68 + kk + lt];
                unsigned b1 = Ks[rn * 68 + kk + lt + 4];
                mma8(sc[0][ni], a[0][0], a[0][1], a[0][2], a[0][3], b0, b1);
                mma8(sc[1][ni], a[1][0], a[1][1], a[1][2], a[1][3], b0, b1);
            }
        }
        #pragma unroll
        for (int mi = 0; mi < 2; mi++) {
            #pragma unroll
            for (int ni = 0; ni < 2; ni++) {
                int r = mw + mi * 16 + lg, cc = nws + ni * 8 + 2 * lt;
                S[r * 68 + cc]           = sc[mi][ni][0] * 0.125f;
                S[r * 68 + cc + 1]       = sc[mi][ni][1] * 0.125f;
                S[(r + 8) * 68 + cc]     = sc[mi][ni][2] * 0.125f;
                S[(r + 8) * 68 + cc + 1] = sc[mi][ni][3] * 0.125f;
            }
        }
        __syncthreads();

        // ---- online softmax: 4 threads/row, 16 cols each; write P as tf32 ----
        {
            int r = t >> 2, c0 = (t & 3) * 16;
            float* srow = S + r * 68 + c0;
            unsigned* prow = (unsigned*)srow;
            float mloc = srow[0];
            #pragma unroll
            for (int c = 1; c < 16; c++) mloc = fmaxf(mloc, srow[c]);
            mloc = fmaxf(mloc, __shfl_xor_sync(0xffffffffu, mloc, 1));
            mloc = fmaxf(mloc, __shfl_xor_sync(0xffffffffu, mloc, 2));
            float mold = mrow[r];
            float mnew = fmaxf(mold, mloc);
            float sum = 0.f;
            #pragma unroll
            for (int c = 0; c < 16; c++) {
                float p = __expf(srow[c] - mnew);
                sum += p;
                prow[c] = f2tf(p);
            }
            sum += __shfl_xor_sync(0xffffffffu, sum, 1);
            sum += __shfl_xor_sync(0xffffffffu, sum, 2);
            if ((t & 3) == 0) {
                float al = __expf(mold - mnew);
                arow[r] = al;
                mrow[r] = mnew;
                lrow[r] = lrow[r] * al + sum;
            }
        }
        __syncthreads();

        // ---- rescale O, then O += P @ V ----
        {
            float al[2][2];
            #pragma unroll
            for (int mi = 0; mi < 2; mi++) {
                al[mi][0] = arow[mw + mi * 16 + lg];
                al[mi][1] = arow[mw + mi * 16 + lg + 8];
            }
            #pragma unroll
            for (int mi = 0; mi < 2; mi++)
                #pragma unroll
                for (int ni = 0; ni < 8; ni++) {
                    O[mi][ni][0] *= al[mi][0];
                    O[mi][ni][1] *= al[mi][0];
                    O[mi][ni][2] *= al[mi][1];
                    O[mi][ni][3] *= al[mi][1];
                }

            unsigned* P = (unsigned*)S;
            #pragma unroll
            for (int ks = 0; ks < 8; ks++) {
                const int kk = ks * 8;
                unsigned a[2][4];
                #pragma unroll
                for (int mi = 0; mi < 2; mi++) {
                    int r = mw + mi * 16 + lg;
                    a[mi][0] = P[r * 68 + kk + lt];
                    a[mi][1] = P[(r + 8) * 68 + kk + lt];
                    a[mi][2] = P[r * 68 + kk + lt + 4];
                    a[mi][3] = P[(r + 8) * 68 + kk + lt + 4];
                }
                #pragma unroll
                for (int ni = 0; ni < 8; ni++) {
                    int cn = nwp + ni * 8 + lg;
                    unsigned b0 = Vs[(kk + lt) * 264 + cn];
                    unsigned b1 = Vs[(kk + lt + 4) * 264 + cn];
                    mma8(O[0][ni], a[0][0], a[0][1], a[0][2], a[0][3], b0, b1);
                    mma8(O[1][ni], a[1][0], a[1][1], a[1][2], a[1][3], b0, b1);
                }
            }
        }
        __syncthreads();
    }

    // ---- normalize and write out ----
    #pragma unroll
    for (int mi = 0; mi < 2; mi++) {
        int r0 = mw + mi * 16 + lg;
        float li0 = 1.0f / lrow[r0];
        float li1 = 1.0f / lrow[r0 + 8];
        float* o0 = out + (size_t)(b * SEQ + q0 + r0) * COUT;
        float* o1 = out + (size_t)(b * SEQ + q0 + r0 + 8) * COUT;
        #pragma unroll
        for (int ni = 0; ni < 8; ni++) {
            int col = nwp + ni * 8 + 2 * lt;
            float2 v0, v1;
            v0.x = O[mi][ni][0] * li0; v0.y = O[mi][ni][1] * li0;
            v1.x = O[mi][ni][2] * li1; v1.y = O[mi][ni][3] * li1;
            *(float2*)(o0 + col) = v0;
            *(float2*)(o1 + col) = v1;
        }
    }
}

// ---------------------------------------------------------------------------
// Copy keep rows (identity) into the output.
// ---------------------------------------------------------------------------
__global__ void __launch_bounds__(256) copy_keep_kernel(
    const float* __restrict__ f, float* __restrict__ out)
{
    int idx = blockIdx.x * blockDim.x + threadIdx.x;       // float4 index
    int kr = idx >> 6;
    int c  = (idx & 63) * 4;
    int b  = kr >> 12;
    int j  = kr & (NK - 1);
    size_t grow = (size_t)b * SEQ + NF + j;
    *(float4*)(out + grow * COUT + c) = *(const float4*)(f + grow * CIN + c);
}

// ---------------------------------------------------------------------------
extern "C" void kernel_launch(void* const* d_in, const int* in_sizes, int n_in,
                              void* d_out, int out_size)
{
    const float* features = (const float*)d_in[0];
    const float* Wq = (const float*)d_in[2];
    const float* bq = (const float*)d_in[3];
    const float* Wk = (const float*)d_in[4];
    const float* bk = (const float*)d_in[5];
    const float* Wv = (const float*)d_in[6];
    const float* bv = (const float*)d_in[7];
    float* out = (float*)d_out;

    void *pq, *pk, *pv;
    cudaGetSymbolAddress(&pq, g_q);
    cudaGetSymbolAddress(&pk, g_k);
    cudaGetSymbolAddress(&pv, g_v);

    // Projections (tf32 tensor cores)
    proj_tc<0><<<dim3(1, (NB * NF) / 128), 256>>>(features, Wq, bq, (float*)pq, CKQ);
    proj_tc<1><<<dim3(1, (NB * NK) / 128), 256>>>(features, Wk, bk, (float*)pk, CKQ);
    proj_tc<1><<<dim3(COUT / 64, (NB * NK) / 128), 256>>>(features, Wv, bv, (float*)pv, COUT);

    // Identity copy of keep rows
    copy_keep_kernel<<<(NB * NK * COUT / 4) / 256, 256>>>(features, out);

    // Attention (tf32 tensor cores)
    const int smem_bytes = (64 * 68 * 2 + 64 * 264) * 4 + 64 * 68 * 4 + 3 * 64 * 4;
    cudaFuncSetAttribute(attn_tc, cudaFuncAttributeMaxDynamicSharedMemorySize, smem_bytes);
    attn_tc<<<dim3(NF / 64, NB), 256, smem_bytes>>>(
        (const float*)pq, (const float*)pk, (const float*)pv, out);
}